// round 1
// baseline (speedup 1.0000x reference)
#include <cuda_runtime.h>
#include <math.h>

#define S_LEN  1024
#define BATCH  4
#define DMODEL 1024
#define NHEAD  16
#define DHEAD  64

// ---------------- device scratch (no runtime allocation allowed) ----------------
__device__ float g_Wt[DMODEL * 3 * DMODEL];          // packed QKV weight [d][n], n = which*1024 + h*64 + k
__device__ float g_bias[3 * DMODEL];                 // packed QKV bias
__device__ float g_qkv[S_LEN * BATCH * 3 * DMODEL];  // [row = s*B+b][n]
__device__ float g_concat[S_LEN * BATCH * DMODEL];   // attention output, [row][h*64+d]

// ---------------- weight packing ----------------
__global__ void pack_w_kernel(const float* __restrict__ Wq, const float* __restrict__ Wk,
                              const float* __restrict__ Wv, const float* __restrict__ bq,
                              const float* __restrict__ bk, const float* __restrict__ bv) {
    int idx = blockIdx.x * blockDim.x + threadIdx.x;
    const int total = DMODEL * 3 * DMODEL;
    if (idx < total) {
        int d = idx / (3 * DMODEL);
        int n = idx % (3 * DMODEL);
        int which = n >> 10;
        int r = n & 1023;
        const float* W = (which == 0) ? Wq : (which == 1) ? Wk : Wv;
        int h = r >> 6, kk = r & 63;
        g_Wt[idx] = W[(h * DMODEL + d) * DHEAD + kk];
    }
    if (idx < 3 * DMODEL) {
        int which = idx >> 10;
        int r = idx & 1023;
        const float* bb = (which == 0) ? bq : (which == 1) ? bk : bv;
        g_bias[idx] = bb[r];
    }
}

// ---------------- generic 128x128x16 SGEMM body (256 threads, 8x8 micro-tile) ----------------
__device__ __forceinline__ void sgemm_body(
    const float* __restrict__ A, const float* __restrict__ B,
    const float* __restrict__ bias, float* __restrict__ C,
    int K, int lda, int ldb, int ldc, int m0, int n0)
{
    __shared__ float As[16][132];   // transposed A tile: As[k][m]
    __shared__ float Bs[16][132];   // Bs[k][n]

    const int tid = threadIdx.x;
    const int tx = tid & 15, ty = tid >> 4;

    float acc[8][8];
#pragma unroll
    for (int i = 0; i < 8; i++)
#pragma unroll
        for (int j = 0; j < 8; j++) acc[i][j] = 0.f;

    const int arow = tid >> 2;          // 0..63
    const int acol = (tid & 3) << 2;    // 0,4,8,12
    const int brow = tid >> 5;          // 0..7
    const int bcol = (tid & 31) << 2;   // 0..124

    const float* Ap0 = A + (size_t)(m0 + arow) * lda + acol;
    const float* Ap1 = Ap0 + (size_t)64 * lda;
    const float* Bp  = B + (size_t)brow * ldb + n0 + bcol;

    for (int k0 = 0; k0 < K; k0 += 16) {
        float4 a0 = *(const float4*)(Ap0 + k0);
        float4 a1 = *(const float4*)(Ap1 + k0);
        float4 b0 = *(const float4*)(Bp + (size_t)k0 * ldb);
        float4 b1 = *(const float4*)(Bp + (size_t)(k0 + 8) * ldb);
        __syncthreads();
        As[acol + 0][arow] = a0.x; As[acol + 1][arow] = a0.y;
        As[acol + 2][arow] = a0.z; As[acol + 3][arow] = a0.w;
        As[acol + 0][arow + 64] = a1.x; As[acol + 1][arow + 64] = a1.y;
        As[acol + 2][arow + 64] = a1.z; As[acol + 3][arow + 64] = a1.w;
        *(float4*)&Bs[brow][bcol]     = b0;
        *(float4*)&Bs[brow + 8][bcol] = b1;
        __syncthreads();
#pragma unroll
        for (int kk = 0; kk < 16; ++kk) {
            float af[8], bf[8];
            *(float4*)(af)     = *(const float4*)&As[kk][ty * 4];
            *(float4*)(af + 4) = *(const float4*)&As[kk][64 + ty * 4];
            *(float4*)(bf)     = *(const float4*)&Bs[kk][tx * 4];
            *(float4*)(bf + 4) = *(const float4*)&Bs[kk][64 + tx * 4];
#pragma unroll
            for (int i = 0; i < 8; i++)
#pragma unroll
                for (int j = 0; j < 8; j++)
                    acc[i][j] = fmaf(af[i], bf[j], acc[i][j]);
        }
    }

#pragma unroll
    for (int gi = 0; gi < 2; gi++)
#pragma unroll
        for (int ii = 0; ii < 4; ii++) {
            int row = m0 + gi * 64 + ty * 4 + ii;
#pragma unroll
            for (int gj = 0; gj < 2; gj++) {
                int col = n0 + gj * 64 + tx * 4;
                float4 r;
                r.x = acc[gi * 4 + ii][gj * 4 + 0] + bias[col + 0];
                r.y = acc[gi * 4 + ii][gj * 4 + 1] + bias[col + 1];
                r.z = acc[gi * 4 + ii][gj * 4 + 2] + bias[col + 2];
                r.w = acc[gi * 4 + ii][gj * 4 + 3] + bias[col + 3];
                *(float4*)&C[(size_t)row * ldc + col] = r;
            }
        }
}

// GEMM 1: qkv[4096,3072] = {query|key|value}[4096,1024] @ g_Wt[1024,3072] + g_bias
__global__ void gemm_qkv_kernel(const float* __restrict__ q, const float* __restrict__ k,
                                const float* __restrict__ v) {
    int n0 = blockIdx.x * 128;
    int m0 = blockIdx.y * 128;
    const float* A = (n0 < 1024) ? q : (n0 < 2048) ? k : v;
    sgemm_body(A, g_Wt, g_bias, g_qkv, DMODEL, DMODEL, 3 * DMODEL, 3 * DMODEL, m0, n0);
}

// GEMM 3: out[4096,1024] = g_concat[4096,1024] @ Wo[1024,1024] + bo
__global__ void gemm_out_kernel(const float* __restrict__ Wo, const float* __restrict__ bo,
                                float* __restrict__ out) {
    int n0 = blockIdx.x * 128;
    int m0 = blockIdx.y * 128;
    sgemm_body(g_concat, Wo, bo, out, DMODEL, DMODEL, DMODEL, DMODEL, m0, n0);
}

// ---------------- fused flash-style attention ----------------
// grid: (S/64, H, B); block: 256 threads (tx = tid&15 over j/d, ty = tid>>4 over i)
// Each block: 64 query rows for one (b,h). Loops over key tiles of 32 with online softmax.
__global__ void attn_kernel(const int* __restrict__ key_mask) {
    const int b  = blockIdx.z;
    const int h  = blockIdx.y;
    const int i0 = blockIdx.x * 64;

    __shared__ float Qs[64][68];   // [d][i]
    __shared__ float Ks[64][36];   // [d][j]
    __shared__ float Vs[32][68];   // [j][d]
    __shared__ float Ps[64][36];   // [i][j]
    __shared__ float msk[32];

    const int tid = threadIdx.x;
    const int tx = tid & 15, ty = tid >> 4;

    // Load Q tile transposed: Qs[d][i]
    {
        const int li = tid >> 4;         // 0..15
        const int c  = (tid & 15) << 2;  // 0..60
#pragma unroll
        for (int r = 0; r < 4; ++r) {
            int i = li + 16 * r;
            float4 qv = *(const float4*)&g_qkv[(size_t)((i0 + i) * BATCH + b) * (3 * DMODEL) + h * 64 + c];
            Qs[c + 0][i] = qv.x; Qs[c + 1][i] = qv.y;
            Qs[c + 2][i] = qv.z; Qs[c + 3][i] = qv.w;
        }
    }

    float m_run[4], l_run[4], o_acc[4][4];
#pragma unroll
    for (int ii = 0; ii < 4; ++ii) {
        m_run[ii] = -1e30f;
        l_run[ii] = 0.f;
#pragma unroll
        for (int dd = 0; dd < 4; ++dd) o_acc[ii][dd] = 0.f;
    }
    const float scale = 0.125f;  // 1/sqrt(64)

    for (int jt = 0; jt < S_LEN / 32; ++jt) {
        const int j0 = jt * 32;
        __syncthreads();   // protect Ks/Vs/Ps from previous iteration's readers
        {
            const int lj = tid >> 4;
            const int c  = (tid & 15) << 2;
#pragma unroll
            for (int r = 0; r < 2; ++r) {
                int j = lj + 16 * r;
                size_t rowoff = (size_t)((j0 + j) * BATCH + b) * (3 * DMODEL) + h * 64 + c;
                float4 kv = *(const float4*)&g_qkv[1024 + rowoff];
                Ks[c + 0][j] = kv.x; Ks[c + 1][j] = kv.y;
                Ks[c + 2][j] = kv.z; Ks[c + 3][j] = kv.w;
                float4 vv = *(const float4*)&g_qkv[2048 + rowoff];
                *(float4*)&Vs[j][c] = vv;
            }
            if (tid < 32)
                msk[tid] = key_mask[(j0 + tid) * BATCH + b] ? -1e18f : 0.f;
        }
        __syncthreads();

        // ---- scores: s[ii][jj] for i = ty*4+ii, j = tx*2+jj ----
        float s[4][2];
#pragma unroll
        for (int ii = 0; ii < 4; ++ii) { s[ii][0] = 0.f; s[ii][1] = 0.f; }
#pragma unroll
        for (int d = 0; d < 64; ++d) {
            float4 qv = *(const float4*)&Qs[d][ty * 4];
            float2 kv = *(const float2*)&Ks[d][tx * 2];
            s[0][0] = fmaf(qv.x, kv.x, s[0][0]); s[0][1] = fmaf(qv.x, kv.y, s[0][1]);
            s[1][0] = fmaf(qv.y, kv.x, s[1][0]); s[1][1] = fmaf(qv.y, kv.y, s[1][1]);
            s[2][0] = fmaf(qv.z, kv.x, s[2][0]); s[2][1] = fmaf(qv.z, kv.y, s[2][1]);
            s[3][0] = fmaf(qv.w, kv.x, s[3][0]); s[3][1] = fmaf(qv.w, kv.y, s[3][1]);
        }

        // ---- online softmax update ----
        const float mk0 = msk[tx * 2], mk1 = msk[tx * 2 + 1];
#pragma unroll
        for (int ii = 0; ii < 4; ++ii) {
            float v0 = s[ii][0] * scale + mk0;
            float v1 = s[ii][1] * scale + mk1;
            float mx = fmaxf(v0, v1);
#pragma unroll
            for (int off = 8; off >= 1; off >>= 1)
                mx = fmaxf(mx, __shfl_xor_sync(0xffffffffu, mx, off, 16));
            float m_new = fmaxf(m_run[ii], mx);
            float p0 = __expf(v0 - m_new);
            float p1 = __expf(v1 - m_new);
            Ps[ty * 4 + ii][tx * 2 + 0] = p0;
            Ps[ty * 4 + ii][tx * 2 + 1] = p1;
            float rs = p0 + p1;
#pragma unroll
            for (int off = 8; off >= 1; off >>= 1)
                rs += __shfl_xor_sync(0xffffffffu, rs, off, 16);
            float alpha = __expf(m_run[ii] - m_new);
            l_run[ii] = l_run[ii] * alpha + rs;
            m_run[ii] = m_new;
#pragma unroll
            for (int dd = 0; dd < 4; ++dd) o_acc[ii][dd] *= alpha;
        }
        __syncthreads();   // Ps complete before PV

        // ---- O += P @ V : thread covers i = ty*4+ii, d = tx*4+dd ----
#pragma unroll 4
        for (int j = 0; j < 32; ++j) {
            float4 vv = *(const float4*)&Vs[j][tx * 4];
            float p0 = Ps[ty * 4 + 0][j];
            float p1 = Ps[ty * 4 + 1][j];
            float p2 = Ps[ty * 4 + 2][j];
            float p3 = Ps[ty * 4 + 3][j];
            o_acc[0][0] = fmaf(p0, vv.x, o_acc[0][0]); o_acc[0][1] = fmaf(p0, vv.y, o_acc[0][1]);
            o_acc[0][2] = fmaf(p0, vv.z, o_acc[0][2]); o_acc[0][3] = fmaf(p0, vv.w, o_acc[0][3]);
            o_acc[1][0] = fmaf(p1, vv.x, o_acc[1][0]); o_acc[1][1] = fmaf(p1, vv.y, o_acc[1][1]);
            o_acc[1][2] = fmaf(p1, vv.z, o_acc[1][2]); o_acc[1][3] = fmaf(p1, vv.w, o_acc[1][3]);
            o_acc[2][0] = fmaf(p2, vv.x, o_acc[2][0]); o_acc[2][1] = fmaf(p2, vv.y, o_acc[2][1]);
            o_acc[2][2] = fmaf(p2, vv.z, o_acc[2][2]); o_acc[2][3] = fmaf(p2, vv.w, o_acc[2][3]);
            o_acc[3][0] = fmaf(p3, vv.x, o_acc[3][0]); o_acc[3][1] = fmaf(p3, vv.y, o_acc[3][1]);
            o_acc[3][2] = fmaf(p3, vv.z, o_acc[3][2]); o_acc[3][3] = fmaf(p3, vv.w, o_acc[3][3]);
        }
    }

    // ---- epilogue: normalize and write concat ----
#pragma unroll
    for (int ii = 0; ii < 4; ++ii) {
        float inv = 1.f / l_run[ii];
        int i = i0 + ty * 4 + ii;
        float4 r;
        r.x = o_acc[ii][0] * inv;
        r.y = o_acc[ii][1] * inv;
        r.z = o_acc[ii][2] * inv;
        r.w = o_acc[ii][3] * inv;
        *(float4*)&g_concat[(size_t)(i * BATCH + b) * DMODEL + h * 64 + tx * 4] = r;
    }
}

// ---------------- entry point ----------------
extern "C" void kernel_launch(void* const* d_in, const int* in_sizes, int n_in,
                              void* d_out, int out_size) {
    const float* query    = (const float*)d_in[0];
    const float* key      = (const float*)d_in[1];
    const float* value    = (const float*)d_in[2];
    const int*   key_mask = (const int*)  d_in[3];
    const float* Wq = (const float*)d_in[4];
    const float* bq = (const float*)d_in[5];
    const float* Wk = (const float*)d_in[6];
    const float* bk = (const float*)d_in[7];
    const float* Wv = (const float*)d_in[8];
    const float* bv = (const float*)d_in[9];
    const float* Wo = (const float*)d_in[10];
    const float* bo = (const float*)d_in[11];
    float* out = (float*)d_out;

    pack_w_kernel<<<(DMODEL * 3 * DMODEL + 255) / 256, 256>>>(Wq, Wk, Wv, bq, bk, bv);
    gemm_qkv_kernel<<<dim3(3 * DMODEL / 128, S_LEN * BATCH / 128), 256>>>(query, key, value);
    attn_kernel<<<dim3(S_LEN / 64, NHEAD, BATCH), 256>>>(key_mask);
    gemm_out_kernel<<<dim3(DMODEL / 128, S_LEN * BATCH / 128), 256>>>(Wo, bo, out);
}

// round 2
// speedup vs baseline: 1.6049x; 1.6049x over previous
#include <cuda_runtime.h>
#include <math.h>

#define S_LEN  1024
#define BATCH  4
#define DMODEL 1024
#define NHEAD  16
#define DHEAD  64

// ---------------- device scratch (no runtime allocation allowed) ----------------
__device__ float g_Wt[DMODEL * 3 * DMODEL];          // packed QKV weight [d][n], n = which*1024 + h*64 + k
__device__ float g_bias[3 * DMODEL];                 // packed QKV bias
__device__ float g_qkv[S_LEN * BATCH * 3 * DMODEL];  // [row = s*B+b][n]
__device__ float g_concat[S_LEN * BATCH * DMODEL];   // attention output, [row][h*64+d]

// ---------------- helpers ----------------
__device__ __forceinline__ unsigned f2tf(float f) {
    unsigned u;
    asm("cvt.rna.tf32.f32 %0, %1;" : "=r"(u) : "f"(f));
    return u;
}

#define MMA_TF32(d, a, b)                                                        \
    asm volatile(                                                                \
        "mma.sync.aligned.m16n8k8.row.col.f32.tf32.tf32.f32 "                    \
        "{%0,%1,%2,%3}, {%4,%5,%6,%7}, {%8,%9}, {%0,%1,%2,%3};"                  \
        : "+f"((d)[0]), "+f"((d)[1]), "+f"((d)[2]), "+f"((d)[3])                 \
        : "r"((a)[0]), "r"((a)[1]), "r"((a)[2]), "r"((a)[3]),                    \
          "r"((b)[0]), "r"((b)[1]))

// ---------------- weight packing ----------------
__global__ void pack_w_kernel(const float* __restrict__ Wq, const float* __restrict__ Wk,
                              const float* __restrict__ Wv, const float* __restrict__ bq,
                              const float* __restrict__ bk, const float* __restrict__ bv) {
    int idx = blockIdx.x * blockDim.x + threadIdx.x;
    const int total = DMODEL * 3 * DMODEL;
    if (idx < total) {
        int d = idx / (3 * DMODEL);
        int n = idx % (3 * DMODEL);
        int which = n >> 10;
        int r = n & 1023;
        const float* W = (which == 0) ? Wq : (which == 1) ? Wk : Wv;
        int h = r >> 6, kk = r & 63;
        g_Wt[idx] = W[(h * DMODEL + d) * DHEAD + kk];
    }
    if (idx < 3 * DMODEL) {
        int which = idx >> 10;
        int r = idx & 1023;
        const float* bb = (which == 0) ? bq : (which == 1) ? bk : bv;
        g_bias[idx] = bb[r];
    }
}

// ---------------- TF32 tensor-core GEMM: 128x128x32 block tile, 8 warps ----------------
// C[m0..+128][n0..+128] = A[128 x K] @ B[K x 128] + bias, fp32 in/out, tf32 mma.
__device__ __forceinline__ void gemm_tf32_body(
    const float* __restrict__ A, const float* __restrict__ B,
    const float* __restrict__ bias, float* __restrict__ C,
    int K, int lda, int ldb, int ldc, int m0, int n0)
{
    __shared__ unsigned As[128][36];   // [m][k], pad 4 -> conflict-free frag loads
    __shared__ unsigned Bs[32][136];   // [k][n], pad 8 -> conflict-free frag loads

    const int tid  = threadIdx.x;
    const int lane = tid & 31;
    const int wid  = tid >> 5;          // 0..7
    const int wm   = (wid >> 2) * 64;   // warp m-offset: 0 or 64
    const int wn   = (wid & 3) * 32;    // warp n-offset: 0,32,64,96
    const int gid  = lane >> 2;         // 0..7
    const int tig  = lane & 3;          // 0..3

    float acc[4][4][4];
#pragma unroll
    for (int mt = 0; mt < 4; ++mt)
#pragma unroll
        for (int nt = 0; nt < 4; ++nt)
#pragma unroll
            for (int r = 0; r < 4; ++r) acc[mt][nt][r] = 0.f;

    // global-load mapping
    const int arow = tid >> 3;               // 0..31 (x4 rows)
    const int acol = (tid & 7) << 2;         // 0..28
    const int brow = tid >> 5;               // 0..7  (x4 rows)
    const int bcol = (tid & 31) << 2;        // 0..124

    const float* Ap = A + (size_t)(m0 + arow) * lda + acol;
    const float* Bp = B + (size_t)brow * ldb + n0 + bcol;

    for (int k0 = 0; k0 < K; k0 += 32) {
        float4 ag[4], bg[4];
#pragma unroll
        for (int r = 0; r < 4; ++r)
            ag[r] = *(const float4*)(Ap + (size_t)(32 * r) * lda + k0);
#pragma unroll
        for (int r = 0; r < 4; ++r)
            bg[r] = *(const float4*)(Bp + (size_t)(k0 + 8 * r) * ldb);

        __syncthreads();
#pragma unroll
        for (int r = 0; r < 4; ++r) {
            unsigned* d = &As[arow + 32 * r][acol];
            d[0] = f2tf(ag[r].x); d[1] = f2tf(ag[r].y);
            d[2] = f2tf(ag[r].z); d[3] = f2tf(ag[r].w);
        }
#pragma unroll
        for (int r = 0; r < 4; ++r) {
            unsigned* d = &Bs[brow + 8 * r][bcol];
            d[0] = f2tf(bg[r].x); d[1] = f2tf(bg[r].y);
            d[2] = f2tf(bg[r].z); d[3] = f2tf(bg[r].w);
        }
        __syncthreads();

#pragma unroll
        for (int kk = 0; kk < 4; ++kk) {
            const int kb = kk * 8;
            unsigned af[4][4], bf[4][2];
#pragma unroll
            for (int mt = 0; mt < 4; ++mt) {
                int r = wm + mt * 16 + gid;
                af[mt][0] = As[r][kb + tig];
                af[mt][1] = As[r + 8][kb + tig];
                af[mt][2] = As[r][kb + tig + 4];
                af[mt][3] = As[r + 8][kb + tig + 4];
            }
#pragma unroll
            for (int nt = 0; nt < 4; ++nt) {
                int c = wn + nt * 8 + gid;
                bf[nt][0] = Bs[kb + tig][c];
                bf[nt][1] = Bs[kb + tig + 4][c];
            }
#pragma unroll
            for (int mt = 0; mt < 4; ++mt)
#pragma unroll
                for (int nt = 0; nt < 4; ++nt)
                    MMA_TF32(acc[mt][nt], af[mt], bf[nt]);
        }
    }

    // epilogue: D fragment c0/c1 at (row=gid, col=2*tig), c2/c3 at (row=gid+8)
#pragma unroll
    for (int mt = 0; mt < 4; ++mt) {
        int row0 = m0 + wm + mt * 16 + gid;
#pragma unroll
        for (int nt = 0; nt < 4; ++nt) {
            int col = n0 + wn + nt * 8 + 2 * tig;
            float b0 = bias[col], b1 = bias[col + 1];
            float2 r0 = make_float2(acc[mt][nt][0] + b0, acc[mt][nt][1] + b1);
            float2 r1 = make_float2(acc[mt][nt][2] + b0, acc[mt][nt][3] + b1);
            *(float2*)&C[(size_t)row0 * ldc + col]       = r0;
            *(float2*)&C[(size_t)(row0 + 8) * ldc + col] = r1;
        }
    }
}

// GEMM 1: qkv[4096,3072] = {query|key|value}[4096,1024] @ g_Wt[1024,3072] + g_bias
__global__ void __launch_bounds__(256, 2) gemm_qkv_kernel(
    const float* __restrict__ q, const float* __restrict__ k, const float* __restrict__ v) {
    int n0 = blockIdx.x * 128;
    int m0 = blockIdx.y * 128;
    const float* A = (n0 < 1024) ? q : (n0 < 2048) ? k : v;
    gemm_tf32_body(A, g_Wt, g_bias, g_qkv, DMODEL, DMODEL, 3 * DMODEL, 3 * DMODEL, m0, n0);
}

// GEMM 3: out[4096,1024] = g_concat[4096,1024] @ Wo[1024,1024] + bo
__global__ void __launch_bounds__(256, 2) gemm_out_kernel(
    const float* __restrict__ Wo, const float* __restrict__ bo, float* __restrict__ out) {
    int n0 = blockIdx.x * 128;
    int m0 = blockIdx.y * 128;
    gemm_tf32_body(g_concat, Wo, bo, out, DMODEL, DMODEL, DMODEL, DMODEL, m0, n0);
}

// ---------------- fused flash-style attention (fp32, unchanged this round) ----------------
__global__ void attn_kernel(const int* __restrict__ key_mask) {
    const int b  = blockIdx.z;
    const int h  = blockIdx.y;
    const int i0 = blockIdx.x * 64;

    __shared__ float Qs[64][68];   // [d][i]
    __shared__ float Ks[64][36];   // [d][j]
    __shared__ float Vs[32][68];   // [j][d]
    __shared__ float Ps[64][36];   // [i][j]
    __shared__ float msk[32];

    const int tid = threadIdx.x;
    const int tx = tid & 15, ty = tid >> 4;

    {
        const int li = tid >> 4;
        const int c  = (tid & 15) << 2;
#pragma unroll
        for (int r = 0; r < 4; ++r) {
            int i = li + 16 * r;
            float4 qv = *(const float4*)&g_qkv[(size_t)((i0 + i) * BATCH + b) * (3 * DMODEL) + h * 64 + c];
            Qs[c + 0][i] = qv.x; Qs[c + 1][i] = qv.y;
            Qs[c + 2][i] = qv.z; Qs[c + 3][i] = qv.w;
        }
    }

    float m_run[4], l_run[4], o_acc[4][4];
#pragma unroll
    for (int ii = 0; ii < 4; ++ii) {
        m_run[ii] = -1e30f;
        l_run[ii] = 0.f;
#pragma unroll
        for (int dd = 0; dd < 4; ++dd) o_acc[ii][dd] = 0.f;
    }
    const float scale = 0.125f;

    for (int jt = 0; jt < S_LEN / 32; ++jt) {
        const int j0 = jt * 32;
        __syncthreads();
        {
            const int lj = tid >> 4;
            const int c  = (tid & 15) << 2;
#pragma unroll
            for (int r = 0; r < 2; ++r) {
                int j = lj + 16 * r;
                size_t rowoff = (size_t)((j0 + j) * BATCH + b) * (3 * DMODEL) + h * 64 + c;
                float4 kv = *(const float4*)&g_qkv[1024 + rowoff];
                Ks[c + 0][j] = kv.x; Ks[c + 1][j] = kv.y;
                Ks[c + 2][j] = kv.z; Ks[c + 3][j] = kv.w;
                float4 vv = *(const float4*)&g_qkv[2048 + rowoff];
                *(float4*)&Vs[j][c] = vv;
            }
            if (tid < 32)
                msk[tid] = key_mask[(j0 + tid) * BATCH + b] ? -1e18f : 0.f;
        }
        __syncthreads();

        float s[4][2];
#pragma unroll
        for (int ii = 0; ii < 4; ++ii) { s[ii][0] = 0.f; s[ii][1] = 0.f; }
#pragma unroll
        for (int d = 0; d < 64; ++d) {
            float4 qv = *(const float4*)&Qs[d][ty * 4];
            float2 kv = *(const float2*)&Ks[d][tx * 2];
            s[0][0] = fmaf(qv.x, kv.x, s[0][0]); s[0][1] = fmaf(qv.x, kv.y, s[0][1]);
            s[1][0] = fmaf(qv.y, kv.x, s[1][0]); s[1][1] = fmaf(qv.y, kv.y, s[1][1]);
            s[2][0] = fmaf(qv.z, kv.x, s[2][0]); s[2][1] = fmaf(qv.z, kv.y, s[2][1]);
            s[3][0] = fmaf(qv.w, kv.x, s[3][0]); s[3][1] = fmaf(qv.w, kv.y, s[3][1]);
        }

        const float mk0 = msk[tx * 2], mk1 = msk[tx * 2 + 1];
#pragma unroll
        for (int ii = 0; ii < 4; ++ii) {
            float v0 = s[ii][0] * scale + mk0;
            float v1 = s[ii][1] * scale + mk1;
            float mx = fmaxf(v0, v1);
#pragma unroll
            for (int off = 8; off >= 1; off >>= 1)
                mx = fmaxf(mx, __shfl_xor_sync(0xffffffffu, mx, off, 16));
            float m_new = fmaxf(m_run[ii], mx);
            float p0 = __expf(v0 - m_new);
            float p1 = __expf(v1 - m_new);
            Ps[ty * 4 + ii][tx * 2 + 0] = p0;
            Ps[ty * 4 + ii][tx * 2 + 1] = p1;
            float rs = p0 + p1;
#pragma unroll
            for (int off = 8; off >= 1; off >>= 1)
                rs += __shfl_xor_sync(0xffffffffu, rs, off, 16);
            float alpha = __expf(m_run[ii] - m_new);
            l_run[ii] = l_run[ii] * alpha + rs;
            m_run[ii] = m_new;
#pragma unroll
            for (int dd = 0; dd < 4; ++dd) o_acc[ii][dd] *= alpha;
        }
        __syncthreads();

#pragma unroll 4
        for (int j = 0; j < 32; ++j) {
            float4 vv = *(const float4*)&Vs[j][tx * 4];
            float p0 = Ps[ty * 4 + 0][j];
            float p1 = Ps[ty * 4 + 1][j];
            float p2 = Ps[ty * 4 + 2][j];
            float p3 = Ps[ty * 4 + 3][j];
            o_acc[0][0] = fmaf(p0, vv.x, o_acc[0][0]); o_acc[0][1] = fmaf(p0, vv.y, o_acc[0][1]);
            o_acc[0][2] = fmaf(p0, vv.z, o_acc[0][2]); o_acc[0][3] = fmaf(p0, vv.w, o_acc[0][3]);
            o_acc[1][0] = fmaf(p1, vv.x, o_acc[1][0]); o_acc[1][1] = fmaf(p1, vv.y, o_acc[1][1]);
            o_acc[1][2] = fmaf(p1, vv.z, o_acc[1][2]); o_acc[1][3] = fmaf(p1, vv.w, o_acc[1][3]);
            o_acc[2][0] = fmaf(p2, vv.x, o_acc[2][0]); o_acc[2][1] = fmaf(p2, vv.y, o_acc[2][1]);
            o_acc[2][2] = fmaf(p2, vv.z, o_acc[2][2]); o_acc[2][3] = fmaf(p2, vv.w, o_acc[2][3]);
            o_acc[3][0] = fmaf(p3, vv.x, o_acc[3][0]); o_acc[3][1] = fmaf(p3, vv.y, o_acc[3][1]);
            o_acc[3][2] = fmaf(p3, vv.z, o_acc[3][2]); o_acc[3][3] = fmaf(p3, vv.w, o_acc[3][3]);
        }
    }

#pragma unroll
    for (int ii = 0; ii < 4; ++ii) {
        float inv = 1.f / l_run[ii];
        int i = i0 + ty * 4 + ii;
        float4 r;
        r.x = o_acc[ii][0] * inv;
        r.y = o_acc[ii][1] * inv;
        r.z = o_acc[ii][2] * inv;
        r.w = o_acc[ii][3] * inv;
        *(float4*)&g_concat[(size_t)(i * BATCH + b) * DMODEL + h * 64 + tx * 4] = r;
    }
}

// ---------------- entry point ----------------
extern "C" void kernel_launch(void* const* d_in, const int* in_sizes, int n_in,
                              void* d_out, int out_size) {
    const float* query    = (const float*)d_in[0];
    const float* key      = (const float*)d_in[1];
    const float* value    = (const float*)d_in[2];
    const int*   key_mask = (const int*)  d_in[3];
    const float* Wq = (const float*)d_in[4];
    const float* bq = (const float*)d_in[5];
    const float* Wk = (const float*)d_in[6];
    const float* bk = (const float*)d_in[7];
    const float* Wv = (const float*)d_in[8];
    const float* bv = (const float*)d_in[9];
    const float* Wo = (const float*)d_in[10];
    const float* bo = (const float*)d_in[11];
    float* out = (float*)d_out;

    pack_w_kernel<<<(DMODEL * 3 * DMODEL + 255) / 256, 256>>>(Wq, Wk, Wv, bq, bk, bv);
    gemm_qkv_kernel<<<dim3(3 * DMODEL / 128, S_LEN * BATCH / 128), 256>>>(query, key, value);
    attn_kernel<<<dim3(S_LEN / 64, NHEAD, BATCH), 256>>>(key_mask);
    gemm_out_kernel<<<dim3(DMODEL / 128, S_LEN * BATCH / 128), 256>>>(Wo, bo, out);
}

// round 3
// speedup vs baseline: 3.0315x; 1.8889x over previous
#include <cuda_runtime.h>
#include <math.h>

#define S_LEN  1024
#define BATCH  4
#define DMODEL 1024
#define NHEAD  16
#define DHEAD  64

// ---------------- device scratch (no runtime allocation allowed) ----------------
__device__ float g_Wt[DMODEL * 3 * DMODEL];          // packed QKV weight [d][n]
__device__ float g_bias[3 * DMODEL];                 // packed QKV bias
// head-major qkv: idx = (((which*BATCH + b)*NHEAD + h)*S_LEN + s)*DHEAD + d
__device__ float g_qkv[3 * BATCH * NHEAD * S_LEN * DHEAD];
__device__ float g_concat[S_LEN * BATCH * DMODEL];   // [row = s*B+b][h*64+d]

// ---------------- helpers ----------------
__device__ __forceinline__ unsigned f2tf(float f) {
    unsigned u;
    asm("cvt.rna.tf32.f32 %0, %1;" : "=r"(u) : "f"(f));
    return u;
}

#define MMA_TF32(d, a, b)                                                        \
    asm volatile(                                                                \
        "mma.sync.aligned.m16n8k8.row.col.f32.tf32.tf32.f32 "                    \
        "{%0,%1,%2,%3}, {%4,%5,%6,%7}, {%8,%9}, {%0,%1,%2,%3};"                  \
        : "+f"((d)[0]), "+f"((d)[1]), "+f"((d)[2]), "+f"((d)[3])                 \
        : "r"((a)[0]), "r"((a)[1]), "r"((a)[2]), "r"((a)[3]),                    \
          "r"((b)[0]), "r"((b)[1]))

// ---------------- weight packing ----------------
__global__ void pack_w_kernel(const float* __restrict__ Wq, const float* __restrict__ Wk,
                              const float* __restrict__ Wv, const float* __restrict__ bq,
                              const float* __restrict__ bk, const float* __restrict__ bv) {
    int idx = blockIdx.x * blockDim.x + threadIdx.x;
    const int total = DMODEL * 3 * DMODEL;
    if (idx < total) {
        int d = idx / (3 * DMODEL);
        int n = idx % (3 * DMODEL);
        int which = n >> 10;
        int r = n & 1023;
        const float* W = (which == 0) ? Wq : (which == 1) ? Wk : Wv;
        int h = r >> 6, kk = r & 63;
        g_Wt[idx] = W[(h * DMODEL + d) * DHEAD + kk];
    }
    if (idx < 3 * DMODEL) {
        int which = idx >> 10;
        int r = idx & 1023;
        const float* bb = (which == 0) ? bq : (which == 1) ? bk : bv;
        g_bias[idx] = bb[r];
    }
}

// ---------------- TF32 tensor-core GEMM: 128x128x32 block tile, 8 warps ----------------
__device__ __forceinline__ void gemm_tf32_body(
    const float* __restrict__ A, const float* __restrict__ B,
    const float* __restrict__ bias, float* __restrict__ C,
    int K, int lda, int ldb, int ldc, int m0, int n0, int remap)
{
    __shared__ unsigned As[128][36];
    __shared__ unsigned Bs[32][136];

    const int tid  = threadIdx.x;
    const int lane = tid & 31;
    const int wid  = tid >> 5;
    const int wm   = (wid >> 2) * 64;
    const int wn   = (wid & 3) * 32;
    const int gid  = lane >> 2;
    const int tig  = lane & 3;

    float acc[4][4][4];
#pragma unroll
    for (int mt = 0; mt < 4; ++mt)
#pragma unroll
        for (int nt = 0; nt < 4; ++nt)
#pragma unroll
            for (int r = 0; r < 4; ++r) acc[mt][nt][r] = 0.f;

    const int arow = tid >> 3;
    const int acol = (tid & 7) << 2;
    const int brow = tid >> 5;
    const int bcol = (tid & 31) << 2;

    const float* Ap = A + (size_t)(m0 + arow) * lda + acol;
    const float* Bp = B + (size_t)brow * ldb + n0 + bcol;

    for (int k0 = 0; k0 < K; k0 += 32) {
        float4 ag[4], bg[4];
#pragma unroll
        for (int r = 0; r < 4; ++r)
            ag[r] = *(const float4*)(Ap + (size_t)(32 * r) * lda + k0);
#pragma unroll
        for (int r = 0; r < 4; ++r)
            bg[r] = *(const float4*)(Bp + (size_t)(k0 + 8 * r) * ldb);

        __syncthreads();
#pragma unroll
        for (int r = 0; r < 4; ++r) {
            unsigned* d = &As[arow + 32 * r][acol];
            d[0] = f2tf(ag[r].x); d[1] = f2tf(ag[r].y);
            d[2] = f2tf(ag[r].z); d[3] = f2tf(ag[r].w);
        }
#pragma unroll
        for (int r = 0; r < 4; ++r) {
            unsigned* d = &Bs[brow + 8 * r][bcol];
            d[0] = f2tf(bg[r].x); d[1] = f2tf(bg[r].y);
            d[2] = f2tf(bg[r].z); d[3] = f2tf(bg[r].w);
        }
        __syncthreads();

#pragma unroll
        for (int kk = 0; kk < 4; ++kk) {
            const int kb = kk * 8;
            unsigned af[4][4], bf[4][2];
#pragma unroll
            for (int mt = 0; mt < 4; ++mt) {
                int r = wm + mt * 16 + gid;
                af[mt][0] = As[r][kb + tig];
                af[mt][1] = As[r + 8][kb + tig];
                af[mt][2] = As[r][kb + tig + 4];
                af[mt][3] = As[r + 8][kb + tig + 4];
            }
#pragma unroll
            for (int nt = 0; nt < 4; ++nt) {
                int c = wn + nt * 8 + gid;
                bf[nt][0] = Bs[kb + tig][c];
                bf[nt][1] = Bs[kb + tig + 4][c];
            }
#pragma unroll
            for (int mt = 0; mt < 4; ++mt)
#pragma unroll
                for (int nt = 0; nt < 4; ++nt)
                    MMA_TF32(acc[mt][nt], af[mt], bf[nt]);
        }
    }

#pragma unroll
    for (int mt = 0; mt < 4; ++mt) {
        int row0 = m0 + wm + mt * 16 + gid;
#pragma unroll
        for (int nt = 0; nt < 4; ++nt) {
            int col = n0 + wn + nt * 8 + 2 * tig;
            float b0 = bias[col], b1 = bias[col + 1];
            float2 r0 = make_float2(acc[mt][nt][0] + b0, acc[mt][nt][1] + b1);
            float2 r1 = make_float2(acc[mt][nt][2] + b0, acc[mt][nt][3] + b1);
            if (!remap) {
                *(float2*)&C[(size_t)row0 * ldc + col]       = r0;
                *(float2*)&C[(size_t)(row0 + 8) * ldc + col] = r1;
            } else {
                // scatter to head-major layout
                int which = col >> 10, hh = (col >> 6) & 15, d = col & 63;
                int s0 = row0 >> 2, b0i = row0 & 3;
                int row1 = row0 + 8;
                int s1 = row1 >> 2, b1i = row1 & 3;
                size_t i0 = (((size_t)(which * BATCH + b0i) * NHEAD + hh) * S_LEN + s0) * DHEAD + d;
                size_t i1 = (((size_t)(which * BATCH + b1i) * NHEAD + hh) * S_LEN + s1) * DHEAD + d;
                *(float2*)&C[i0] = r0;
                *(float2*)&C[i1] = r1;
            }
        }
    }
}

// GEMM 1: qkv = {q|k|v}[4096,1024] @ g_Wt[1024,3072] + bias -> head-major scatter
__global__ void __launch_bounds__(256, 2) gemm_qkv_kernel(
    const float* __restrict__ q, const float* __restrict__ k, const float* __restrict__ v) {
    int n0 = blockIdx.x * 128;
    int m0 = blockIdx.y * 128;
    const float* A = (n0 < 1024) ? q : (n0 < 2048) ? k : v;
    gemm_tf32_body(A, g_Wt, g_bias, g_qkv, DMODEL, DMODEL, 3 * DMODEL, 0, m0, n0, 1);
}

// GEMM 3: out[4096,1024] = g_concat @ Wo + bo
__global__ void __launch_bounds__(256, 2) gemm_out_kernel(
    const float* __restrict__ Wo, const float* __restrict__ bo, float* __restrict__ out) {
    int n0 = blockIdx.x * 128;
    int m0 = blockIdx.y * 128;
    gemm_tf32_body(g_concat, Wo, bo, out, DMODEL, DMODEL, DMODEL, DMODEL, m0, n0, 0);
}

// ---------------- TF32 MMA flash attention ----------------
// grid (S/128, H, B), 256 threads (8 warps); warp w owns q-rows [w*16, w*16+16).
// smem (u32 words): uQ[128][68], uK[64][68], uV[64][72], uP[128][68], msk[64]f
#define ATTN_SMEM_BYTES ((128 * 68 + 64 * 68 + 64 * 72 + 128 * 68 + 64) * 4)

__global__ void __launch_bounds__(256, 2) attn_kernel(const int* __restrict__ key_mask) {
    extern __shared__ unsigned sm[];
    unsigned* uQ = sm;                       // [128][68] A-operand (ld%32==4)
    unsigned* uK = uQ + 128 * 68;            // [64][68]  read as B via [n][k]
    unsigned* uV = uK + 64 * 68;             // [64][72]  B-operand (ld%32==8)
    unsigned* uP = uV + 64 * 72;             // [128][68] A-operand
    float* msk   = (float*)(uP + 128 * 68);  // [64]

    const int b = blockIdx.z, h = blockIdx.y, i0 = blockIdx.x * 128;
    const int tid = threadIdx.x, lane = tid & 31, wid = tid >> 5;
    const int gid = lane >> 2, tig = lane & 3;
    const int wrow = wid * 16;

    const float* Qg = g_qkv + (((size_t)(0 * BATCH + b) * NHEAD + h) * S_LEN + i0) * DHEAD;
    const float* Kg = g_qkv + (((size_t)(1 * BATCH + b) * NHEAD + h) * S_LEN) * DHEAD;
    const float* Vg = g_qkv + (((size_t)(2 * BATCH + b) * NHEAD + h) * S_LEN) * DHEAD;

    // load Q tile (128x64, contiguous)
    {
        const float4* src = (const float4*)Qg;
#pragma unroll
        for (int r = 0; r < 8; ++r) {
            int f = tid + 256 * r;
            int i = f >> 4, d = (f & 15) << 2;
            float4 v = src[f];
            unsigned* dst = &uQ[i * 68 + d];
            dst[0] = f2tf(v.x); dst[1] = f2tf(v.y); dst[2] = f2tf(v.z); dst[3] = f2tf(v.w);
        }
    }

    float m0 = -1e30f, m1 = -1e30f, l0 = 0.f, l1 = 0.f;
    float o[8][4];
#pragma unroll
    for (int nt = 0; nt < 8; ++nt)
#pragma unroll
        for (int r = 0; r < 4; ++r) o[nt][r] = 0.f;

    for (int jt = 0; jt < S_LEN / 64; ++jt) {
        const int j0 = jt * 64;
        __syncthreads();
        {
            const float4* ks = (const float4*)(Kg + (size_t)j0 * DHEAD);
            const float4* vs = (const float4*)(Vg + (size_t)j0 * DHEAD);
#pragma unroll
            for (int r = 0; r < 4; ++r) {
                int f = tid + 256 * r;
                int j = f >> 4, d = (f & 15) << 2;
                float4 kv = ks[f];
                unsigned* kd = &uK[j * 68 + d];
                kd[0] = f2tf(kv.x); kd[1] = f2tf(kv.y); kd[2] = f2tf(kv.z); kd[3] = f2tf(kv.w);
                float4 vv = vs[f];
                unsigned* vd = &uV[j * 72 + d];
                vd[0] = f2tf(vv.x); vd[1] = f2tf(vv.y); vd[2] = f2tf(vv.z); vd[3] = f2tf(vv.w);
            }
            if (tid < 64)
                msk[tid] = key_mask[(j0 + tid) * BATCH + b] ? -1e18f : 0.f;
        }
        __syncthreads();

        // ---- S = Q @ K^T (per warp: 16x64) ----
        float s[8][4];
#pragma unroll
        for (int nt = 0; nt < 8; ++nt)
#pragma unroll
            for (int r = 0; r < 4; ++r) s[nt][r] = 0.f;
#pragma unroll
        for (int kb = 0; kb < 64; kb += 8) {
            unsigned a[4];
            a[0] = uQ[(wrow + gid) * 68 + kb + tig];
            a[1] = uQ[(wrow + gid + 8) * 68 + kb + tig];
            a[2] = uQ[(wrow + gid) * 68 + kb + tig + 4];
            a[3] = uQ[(wrow + gid + 8) * 68 + kb + tig + 4];
#pragma unroll
            for (int nt = 0; nt < 8; ++nt) {
                unsigned bfr[2];
                bfr[0] = uK[(nt * 8 + gid) * 68 + kb + tig];
                bfr[1] = uK[(nt * 8 + gid) * 68 + kb + tig + 4];
                MMA_TF32(s[nt], a, bfr);
            }
        }

        // ---- scale + mask + online softmax (rows gid, gid+8 of warp tile) ----
        float mx0 = -1e30f, mx1 = -1e30f;
#pragma unroll
        for (int nt = 0; nt < 8; ++nt) {
            float q0 = msk[nt * 8 + 2 * tig], q1 = msk[nt * 8 + 2 * tig + 1];
            s[nt][0] = fmaf(s[nt][0], 0.125f, q0);
            s[nt][1] = fmaf(s[nt][1], 0.125f, q1);
            s[nt][2] = fmaf(s[nt][2], 0.125f, q0);
            s[nt][3] = fmaf(s[nt][3], 0.125f, q1);
            mx0 = fmaxf(mx0, fmaxf(s[nt][0], s[nt][1]));
            mx1 = fmaxf(mx1, fmaxf(s[nt][2], s[nt][3]));
        }
        mx0 = fmaxf(mx0, __shfl_xor_sync(0xffffffffu, mx0, 1));
        mx0 = fmaxf(mx0, __shfl_xor_sync(0xffffffffu, mx0, 2));
        mx1 = fmaxf(mx1, __shfl_xor_sync(0xffffffffu, mx1, 1));
        mx1 = fmaxf(mx1, __shfl_xor_sync(0xffffffffu, mx1, 2));

        float mn0 = fmaxf(m0, mx0), mn1 = fmaxf(m1, mx1);
        float la0 = 0.f, la1 = 0.f;
        unsigned* p0row = &uP[(wrow + gid) * 68];
        unsigned* p1row = &uP[(wrow + gid + 8) * 68];
#pragma unroll
        for (int nt = 0; nt < 8; ++nt) {
            float p0 = __expf(s[nt][0] - mn0);
            float p1 = __expf(s[nt][1] - mn0);
            float p2 = __expf(s[nt][2] - mn1);
            float p3 = __expf(s[nt][3] - mn1);
            la0 += p0 + p1; la1 += p2 + p3;
            int c = nt * 8 + 2 * tig;
            p0row[c] = f2tf(p0); p0row[c + 1] = f2tf(p1);
            p1row[c] = f2tf(p2); p1row[c + 1] = f2tf(p3);
        }
        la0 += __shfl_xor_sync(0xffffffffu, la0, 1);
        la0 += __shfl_xor_sync(0xffffffffu, la0, 2);
        la1 += __shfl_xor_sync(0xffffffffu, la1, 1);
        la1 += __shfl_xor_sync(0xffffffffu, la1, 2);

        float al0 = __expf(m0 - mn0), al1 = __expf(m1 - mn1);
        l0 = l0 * al0 + la0;
        l1 = l1 * al1 + la1;
        m0 = mn0; m1 = mn1;
#pragma unroll
        for (int nt = 0; nt < 8; ++nt) {
            o[nt][0] *= al0; o[nt][1] *= al0;
            o[nt][2] *= al1; o[nt][3] *= al1;
        }
        __syncwarp();  // uP rows are warp-private; order writes before A-frag reads

        // ---- O += P @ V ----
#pragma unroll
        for (int kb = 0; kb < 64; kb += 8) {
            unsigned a[4];
            a[0] = uP[(wrow + gid) * 68 + kb + tig];
            a[1] = uP[(wrow + gid + 8) * 68 + kb + tig];
            a[2] = uP[(wrow + gid) * 68 + kb + tig + 4];
            a[3] = uP[(wrow + gid + 8) * 68 + kb + tig + 4];
#pragma unroll
            for (int nt = 0; nt < 8; ++nt) {
                unsigned bfr[2];
                bfr[0] = uV[(kb + tig) * 72 + nt * 8 + gid];
                bfr[1] = uV[(kb + tig + 4) * 72 + nt * 8 + gid];
                MMA_TF32(o[nt], a, bfr);
            }
        }
    }

    // ---- epilogue ----
    float inv0 = 1.f / l0, inv1 = 1.f / l1;
    int r0 = i0 + wrow + gid;
#pragma unroll
    for (int nt = 0; nt < 8; ++nt) {
        int col = h * 64 + nt * 8 + 2 * tig;
        *(float2*)&g_concat[(size_t)(r0 * BATCH + b) * DMODEL + col] =
            make_float2(o[nt][0] * inv0, o[nt][1] * inv0);
        *(float2*)&g_concat[(size_t)((r0 + 8) * BATCH + b) * DMODEL + col] =
            make_float2(o[nt][2] * inv1, o[nt][3] * inv1);
    }
}

// ---------------- entry point ----------------
extern "C" void kernel_launch(void* const* d_in, const int* in_sizes, int n_in,
                              void* d_out, int out_size) {
    const float* query    = (const float*)d_in[0];
    const float* key      = (const float*)d_in[1];
    const float* value    = (const float*)d_in[2];
    const int*   key_mask = (const int*)  d_in[3];
    const float* Wq = (const float*)d_in[4];
    const float* bq = (const float*)d_in[5];
    const float* Wk = (const float*)d_in[6];
    const float* bk = (const float*)d_in[7];
    const float* Wv = (const float*)d_in[8];
    const float* bv = (const float*)d_in[9];
    const float* Wo = (const float*)d_in[10];
    const float* bo = (const float*)d_in[11];
    float* out = (float*)d_out;

    cudaFuncSetAttribute(attn_kernel, cudaFuncAttributeMaxDynamicSharedMemorySize,
                         ATTN_SMEM_BYTES);

    pack_w_kernel<<<(DMODEL * 3 * DMODEL + 255) / 256, 256>>>(Wq, Wk, Wv, bq, bk, bv);
    gemm_qkv_kernel<<<dim3(3 * DMODEL / 128, S_LEN * BATCH / 128), 256>>>(query, key, value);
    attn_kernel<<<dim3(S_LEN / 128, NHEAD, BATCH), 256, ATTN_SMEM_BYTES>>>(key_mask);
    gemm_out_kernel<<<dim3(DMODEL / 128, S_LEN * BATCH / 128), 256>>>(Wo, bo, out);
}